// round 2
// baseline (speedup 1.0000x reference)
#include <cuda_runtime.h>
#include <cuda_bf16.h>

// Problem constants (fixed by the reference setup_inputs)
#define DIM_K 512
#define MAX_N 16384
#define MAX_M 4096

// Scratch for row norms (no cudaMalloc allowed)
__device__ float g_xsq[MAX_N];
__device__ float g_csq[MAX_M];

// ---------------------------------------------------------------------------
// Row-norm kernels: one block of 128 threads per row, each thread one float4.
// ---------------------------------------------------------------------------
__global__ void xnorm_kernel(const float* __restrict__ x) {
    int row = blockIdx.x;
    const float4* p = reinterpret_cast<const float4*>(x + (size_t)row * DIM_K);
    float4 v = p[threadIdx.x];                 // 128 threads * 4 = 512 elems
    float s = v.x * v.x + v.y * v.y + v.z * v.z + v.w * v.w;
    // warp reduce
    #pragma unroll
    for (int off = 16; off > 0; off >>= 1)
        s += __shfl_down_sync(0xffffffffu, s, off);
    __shared__ float ws[4];
    int wid = threadIdx.x >> 5;
    int lid = threadIdx.x & 31;
    if (lid == 0) ws[wid] = s;
    __syncthreads();
    if (threadIdx.x == 0)
        g_xsq[row] = ws[0] + ws[1] + ws[2] + ws[3];
}

__global__ void cnorm_kernel(const float* __restrict__ c) {
    int row = blockIdx.x;
    const float4* p = reinterpret_cast<const float4*>(c + (size_t)row * DIM_K);
    float4 v = p[threadIdx.x];
    float s = v.x * v.x + v.y * v.y + v.z * v.z + v.w * v.w;
    #pragma unroll
    for (int off = 16; off > 0; off >>= 1)
        s += __shfl_down_sync(0xffffffffu, s, off);
    __shared__ float ws[4];
    int wid = threadIdx.x >> 5;
    int lid = threadIdx.x & 31;
    if (lid == 0) ws[wid] = s;
    __syncthreads();
    if (threadIdx.x == 0)
        g_csq[row] = ws[0] + ws[1] + ws[2] + ws[3];
}

// ---------------------------------------------------------------------------
// Main distance kernel: 128x128 block tile, 8x8 per thread, K-tile 16.
// C[n][m] = xsq[n] + csq[m] - 2 * dot(A[n,:], B[m,:])
// A: [N, 512] row-major, B: [M, 512] row-major (NT GEMM).
// ---------------------------------------------------------------------------
#define BK 16
#define BT 128   // block tile (both dims)
#define TM 8
#define TN 8

__global__ __launch_bounds__(256, 2)
void dist_kernel(const float* __restrict__ A, const float* __restrict__ B,
                 float* __restrict__ C, int N, int M) {
    __shared__ float As[BK][BT];   // [k][row]
    __shared__ float Bs[BK][BT];   // [k][col]

    const int tid = threadIdx.x;
    const int tx = tid & 15;       // 0..15  -> col group
    const int ty = tid >> 4;       // 0..15  -> row group
    const int rowBase = blockIdx.y * BT;
    const int colBase = blockIdx.x * BT;

    float acc[TM][TN];
    #pragma unroll
    for (int i = 0; i < TM; i++)
        #pragma unroll
        for (int j = 0; j < TN; j++)
            acc[i][j] = 0.0f;

    for (int k0 = 0; k0 < DIM_K; k0 += BK) {
        // Load A tile: 128 rows x 16 k = 512 float4 loads, 2 per thread.
        #pragma unroll
        for (int i = 0; i < 2; i++) {
            int idx = tid + i * 256;        // 0..511
            int r   = idx >> 2;             // 0..127
            int kq  = (idx & 3) << 2;       // 0,4,8,12
            float4 v = *reinterpret_cast<const float4*>(
                A + (size_t)(rowBase + r) * DIM_K + k0 + kq);
            As[kq + 0][r] = v.x;
            As[kq + 1][r] = v.y;
            As[kq + 2][r] = v.z;
            As[kq + 3][r] = v.w;
        }
        // Load B tile (same pattern)
        #pragma unroll
        for (int i = 0; i < 2; i++) {
            int idx = tid + i * 256;
            int r   = idx >> 2;
            int kq  = (idx & 3) << 2;
            float4 v = *reinterpret_cast<const float4*>(
                B + (size_t)(colBase + r) * DIM_K + k0 + kq);
            Bs[kq + 0][r] = v.x;
            Bs[kq + 1][r] = v.y;
            Bs[kq + 2][r] = v.z;
            Bs[kq + 3][r] = v.w;
        }
        __syncthreads();

        #pragma unroll
        for (int kk = 0; kk < BK; kk++) {
            float a[TM], b[TN];
            *reinterpret_cast<float4*>(&a[0]) =
                *reinterpret_cast<const float4*>(&As[kk][ty * TM + 0]);
            *reinterpret_cast<float4*>(&a[4]) =
                *reinterpret_cast<const float4*>(&As[kk][ty * TM + 4]);
            *reinterpret_cast<float4*>(&b[0]) =
                *reinterpret_cast<const float4*>(&Bs[kk][tx * TN + 0]);
            *reinterpret_cast<float4*>(&b[4]) =
                *reinterpret_cast<const float4*>(&Bs[kk][tx * TN + 4]);
            #pragma unroll
            for (int i = 0; i < TM; i++)
                #pragma unroll
                for (int j = 0; j < TN; j++)
                    acc[i][j] = fmaf(a[i], b[j], acc[i][j]);
        }
        __syncthreads();
    }

    // Epilogue: dist = xsq + csq - 2*dot
    #pragma unroll
    for (int i = 0; i < TM; i++) {
        int n = rowBase + ty * TM + i;
        float xs = g_xsq[n];
        #pragma unroll
        for (int j = 0; j < TN; j += 4) {
            int m = colBase + tx * TN + j;
            float4 cs = *reinterpret_cast<const float4*>(&g_csq[m]);
            float4 o;
            o.x = xs + cs.x - 2.0f * acc[i][j + 0];
            o.y = xs + cs.y - 2.0f * acc[i][j + 1];
            o.z = xs + cs.z - 2.0f * acc[i][j + 2];
            o.w = xs + cs.w - 2.0f * acc[i][j + 3];
            *reinterpret_cast<float4*>(C + (size_t)n * M + m) = o;
        }
    }
}

// ---------------------------------------------------------------------------
extern "C" void kernel_launch(void* const* d_in, const int* in_sizes, int n_in,
                              void* d_out, int out_size) {
    const float* A = (const float*)d_in[0];   // input  [N, 512]
    const float* B = (const float*)d_in[1];   // centres [M, 512]
    float* C = (float*)d_out;                 // [N, M]

    int N = in_sizes[0] / DIM_K;              // 16384
    int M = in_sizes[1] / DIM_K;              // 4096

    xnorm_kernel<<<N, 128>>>(A);
    cnorm_kernel<<<M, 128>>>(B);

    dim3 grid(M / BT, N / BT);                // (32, 128)
    dist_kernel<<<grid, 256>>>(A, B, C, N, M);
}